// round 13
// baseline (speedup 1.0000x reference)
#include <cuda_runtime.h>
#include <cuda_bf16.h>
#include <math.h>

#define BB 64
#define TT 1024
#define MAXLAG 256
#define NT 512

// Cross-block scratch (device globals — no allocation allowed).
__device__ float g_C[BB * MAXLAG];   // per-(batch,lag) cross-correlation sums
__device__ float g_P[BB];            // per-batch loss
__device__ int   g_cnt[BB];          // per-batch arrival counters (self-resetting)
__device__ int   g_done = 0;         // global finalize counter (self-resetting)

#define FMA2(acc, a, e) \
    asm("fma.rn.f32x2 %0, %1, %2, %0;" : "+l"(acc) : "l"(a), "l"(e))

// Fused kernel, correlation form:
//   S[l] = (Q[L]-Q[l]) + Q[L-l] - 2*C[l],  C[l] = sum_p x_p . x_{p+l}
// grid = (64 batches, 4), 512 threads (16 warps) => 256 blocks (best-measured
// launch shape). Warp w of block (b,y) owns 4 CONSECUTIVE lags 16w+4y+1..+4:
// consecutive => shared end-window loads; the +4y interleave balances work
// across the 4 blocks of a batch to <1%. lag0 = 16w+4y+1 is always ODD, so
// the 16B-aligned window base is lag0-1 (single code path).
// Lane handles 2 consecutive positions/iter: 1 start v2.b64 + 3 end v2.b64 +
// 8 packed dot-FMAs cover 16 point-pairs.
// Tail: last of 4 blocks of batch b scans Q and fits; globally-last reduces.
__global__ __launch_bounds__(NT) void physics_kernel(
    const float* __restrict__ traj,
    const float* __restrict__ alpha_pred,
    const int* __restrict__ lengths,
    float* __restrict__ out)
{
    __shared__ __align__(16) float2 s[TT + 4];     // +4 pad: benign window over-read
    __shared__ float sQ[TT + 1];                   // exclusive prefix of |x|^2
    __shared__ float sh[16];
    __shared__ float wtot[16];
    __shared__ int flag_b, flag_all;

    const int b = blockIdx.x;
    const int y = blockIdx.y;

    // Stage 8KB trajectory: 1 LDG.128 per thread.
    {
        const float4* tr4 = reinterpret_cast<const float4*>(traj) + (size_t)b * (TT / 2);
        float4* s4 = reinterpret_cast<float4*>(s);
        s4[threadIdx.x] = tr4[threadIdx.x];
    }
    if (threadIdx.x < 4) { s[TT + threadIdx.x] = make_float2(0.f, 0.f); }
    __syncthreads();

    const int L    = lengths[b];
    const int w    = threadIdx.x >> 5;
    const int lane = threadIdx.x & 31;

    // ---- correlation phase ----
    const int lag0 = 16 * w + 4 * y + 1;      // odd; lags lag0..lag0+3
    int np0 = L - lag0;   if (np0 < 0) np0 = 0;
    int np3 = np0 - 3;    if (np3 < 0) np3 = 0;
    const int K = np3 >> 6;                   // unguarded 64-position rounds

    const unsigned sbase = (unsigned)__cvta_generic_to_shared(s);
    unsigned addr_a = sbase + 16u * (unsigned)lane;
    unsigned addr_e = sbase + (((unsigned)(lag0 - 1)) << 3) + 16u * (unsigned)lane;

    unsigned long long acc0 = 0, acc1 = 0, acc2 = 0, acc3 = 0;

    for (int t = 0; t < K; ++t) {
        unsigned long long a0, a1, e0, e1, e2, e3, e4, e5;
        asm("ld.shared.v2.b64 {%0,%1}, [%2];"    : "=l"(a0), "=l"(a1) : "r"(addr_a));
        asm("ld.shared.v2.b64 {%0,%1}, [%2];"    : "=l"(e0), "=l"(e1) : "r"(addr_e));
        asm("ld.shared.v2.b64 {%0,%1}, [%2+16];" : "=l"(e2), "=l"(e3) : "r"(addr_e));
        asm("ld.shared.v2.b64 {%0,%1}, [%2+32];" : "=l"(e4), "=l"(e5) : "r"(addr_e));
        // e-window value j corresponds to position p0 + (lag0-1) + j
        FMA2(acc0, a0, e1); FMA2(acc0, a1, e2);   // lag0
        FMA2(acc1, a0, e2); FMA2(acc1, a1, e3);   // lag0+1
        FMA2(acc2, a0, e3); FMA2(acc2, a1, e4);   // lag0+2
        FMA2(acc3, a0, e4); FMA2(acc3, a1, e5);   // lag0+3
        addr_a += 512; addr_e += 512;             // 64 positions * 8 B
    }

    float c0 = __uint_as_float((unsigned)acc0) + __uint_as_float((unsigned)(acc0 >> 32));
    float c1 = __uint_as_float((unsigned)acc1) + __uint_as_float((unsigned)(acc1 >> 32));
    float c2 = __uint_as_float((unsigned)acc2) + __uint_as_float((unsigned)(acc2 >> 32));
    float c3 = __uint_as_float((unsigned)acc3) + __uint_as_float((unsigned)(acc3 >> 32));

    // Guarded tail: positions [64K, np0), <= 3 rounds of 32.
    for (int p = (K << 6) + lane; p < np0; p += 32) {
        const float2 a = s[p];
        {
            const float2 e = s[p + lag0];
            c0 = fmaf(a.x, e.x, c0); c0 = fmaf(a.y, e.y, c0);
        }
        if (p < np0 - 1) {
            const float2 e = s[p + lag0 + 1];
            c1 = fmaf(a.x, e.x, c1); c1 = fmaf(a.y, e.y, c1);
        }
        if (p < np0 - 2) {
            const float2 e = s[p + lag0 + 2];
            c2 = fmaf(a.x, e.x, c2); c2 = fmaf(a.y, e.y, c2);
        }
        if (p < np0 - 3) {
            const float2 e = s[p + lag0 + 3];
            c3 = fmaf(a.x, e.x, c3); c3 = fmaf(a.y, e.y, c3);
        }
    }

#pragma unroll
    for (int o = 16; o; o >>= 1) {
        c0 += __shfl_xor_sync(0xffffffffu, c0, o);
        c1 += __shfl_xor_sync(0xffffffffu, c1, o);
        c2 += __shfl_xor_sync(0xffffffffu, c2, o);
        c3 += __shfl_xor_sync(0xffffffffu, c3, o);
    }
    if (lane == 0) {
        float* dst = &g_C[b * MAXLAG + (lag0 - 1)];
        dst[0] = c0; dst[1] = c1; dst[2] = c2; dst[3] = c3;
        __threadfence();              // writer-side release (16 threads/block)
    }
    __syncthreads();

    // ---- per-batch arrival; last of the 4 blocks fits batch b ----
    if (threadIdx.x == 0) {
        const int old = atomicAdd(&g_cnt[b], 1);
        flag_b = (old == 3) ? 1 : 0;
        if (old == 3) __threadfence();            // acquire side
    }
    __syncthreads();
    if (!flag_b) return;

    // ---- exclusive prefix sum of |x|^2 over [0, TT] (block scan, 512 thr) ----
    {
        const int t = threadIdx.x;
        const float2 v0 = s[2 * t], v1 = s[2 * t + 1];
        const float q0 = v0.x * v0.x + v0.y * v0.y;
        const float q1 = v1.x * v1.x + v1.y * v1.y;
        const float tot = q0 + q1;

        float sc = tot;                              // warp inclusive scan
#pragma unroll
        for (int o = 1; o < 32; o <<= 1) {
            const float n = __shfl_up_sync(0xffffffffu, sc, o);
            if (lane >= o) sc += n;
        }
        if (lane == 31) wtot[w] = sc;
        __syncthreads();
        float base = sc - tot;
#pragma unroll
        for (int k = 0; k < 16; ++k) if (k < w) base += wtot[k];

        sQ[2 * t]     = base;
        sQ[2 * t + 1] = base + q0;
        if (t == NT - 1) sQ[TT] = base + tot;
        __syncthreads();
    }

    // ---- fit: threads 0..255, one per lag ----
    const float alpha = alpha_pred[b];
    float resid = 0.f, m = 0.f;
    if (threadIdx.x < MAXLAG) {
        const int il  = threadIdx.x;
        const int lag = il + 1;
        const int np  = L - lag;
        const int cnt = (np > 0) ? np : 1;             // counts = max(#valid, 1)
        const float C = __ldcg(&g_C[b * MAXLAG + il]); // fresh L2 data
        const float S = (sQ[L] - sQ[lag]) + sQ[(np > 0) ? np : 0] - 2.f * C;
        const float lm = logf(S / (float)cnt + 1e-8f);
        const float ll = logf((float)lag);
        m     = (L > lag) ? 1.f : 0.f;
        resid = lm - alpha * ll;
    }

    // reduction 1: sum(resid*m), sum(m)  (warps 8..15 contribute zeros)
    float sr = resid * m, sm = m;
#pragma unroll
    for (int o = 16; o; o >>= 1) {
        sr += __shfl_xor_sync(0xffffffffu, sr, o);
        sm += __shfl_xor_sync(0xffffffffu, sm, o);
    }
    if (lane == 0 && w < 8) { sh[w] = sr; sh[8 + w] = sm; }
    __syncthreads();
    float srt = 0.f, smt = 0.f;
#pragma unroll
    for (int k = 0; k < 8; ++k) { srt += sh[k]; smt += sh[8 + k]; }

    const float denom     = (smt > 1.f) ? smt : 1.f;
    const float intercept = srt / denom;

    // reduction 2: sum((intercept - resid)^2 * m)
    const float dd = (intercept - resid) * m;
    float se = dd * dd;
#pragma unroll
    for (int o = 16; o; o >>= 1) se += __shfl_xor_sync(0xffffffffu, se, o);
    __syncthreads();
    if (lane == 0 && w < 8) sh[w] = se;
    __syncthreads();

    if (threadIdx.x == 0) {
        float t = 0.f;
#pragma unroll
        for (int k = 0; k < 8; ++k) t += sh[k];
        g_cnt[b] = 0;                       // reset for next graph replay
        g_P[b]   = t / denom;
        __threadfence();                    // publish g_P[b]
        const int old = atomicAdd(&g_done, 1);
        flag_all = (old == BB - 1) ? 1 : 0;
        if (old == BB - 1) __threadfence(); // acquire side
    }
    __syncthreads();
    if (!flag_all) return;

    // ---- globally-last block: mean over batches ----
    if (threadIdx.x < 32) {
        float t = __ldcg(&g_P[threadIdx.x]) + __ldcg(&g_P[threadIdx.x + 32]);
#pragma unroll
        for (int o = 16; o; o >>= 1) t += __shfl_xor_sync(0xffffffffu, t, o);
        if (threadIdx.x == 0) {
            out[0] = t / (float)BB;
            g_done = 0;                     // reset for next graph replay
        }
    }
}

extern "C" void kernel_launch(void* const* d_in, const int* in_sizes, int n_in,
                              void* d_out, int out_size)
{
    const float* alpha_pred = (const float*)d_in[0];
    const float* trajectory = (const float*)d_in[1];
    const int*   lengths    = (const int*)d_in[2];
    float* out = (float*)d_out;

    dim3 g1(BB, 4, 1);
    physics_kernel<<<g1, NT>>>(trajectory, alpha_pred, lengths, out);
}

// round 14
// speedup vs baseline: 1.1186x; 1.1186x over previous
#include <cuda_runtime.h>
#include <cuda_bf16.h>
#include <math.h>

#define BB 64
#define TT 1024
#define MAXLAG 256
#define NT 512

// Cross-block scratch (device globals — no allocation allowed).
__device__ float g_R1[BB * 4];       // per-block partial sum(resid*m)
__device__ float g_R2[BB * 4];       // per-block partial sum(resid^2*m)
__device__ int   g_done = 0;         // global finalize counter (self-resetting)

#define FMA2(acc, a, e) \
    asm("fma.rn.f32x2 %0, %1, %2, %0;" : "+l"(acc) : "l"(a), "l"(e))

// Fused kernel, correlation form + linearized fit:
//   S[l] = (Q[L]-Q[l]) + Q[L-l] - 2*C[l]          (Q = prefix sum of |x|^2)
//   per_traj = (R2 - R1^2/denom)/denom,  R1 = sum resid*m, R2 = sum resid^2*m
// R1,R2 are LINEAR over lags => each block fits its own 64 lags locally and
// publishes two scalars. ONE global rendezvous; last block combines.
// grid = (64 batches, 4), 512 threads. Warp w owns lags 16w+4y+1 .. +4
// (odd lag0 => fixed window alignment). Lane covers 4 consecutive positions
// per iter: 2+4 v2.b64 loads + 16 packed dot-FMAs = 32 point-pairs.
__global__ __launch_bounds__(NT) void physics_kernel(
    const float* __restrict__ traj,
    const float* __restrict__ alpha_pred,
    const int* __restrict__ lengths,
    float* __restrict__ out)
{
    __shared__ __align__(16) float2 s[TT + 4];
    __shared__ float sQ[TT + 1];          // exclusive prefix of |x|^2
    __shared__ float shr[32];             // r1[0..15], r2[16..31]
    __shared__ float wtot[16];
    __shared__ int flag_all;

    const int b = blockIdx.x;
    const int y = blockIdx.y;
    const int t    = threadIdx.x;
    const int w    = t >> 5;
    const int lane = t & 31;

    // ---- prologue: load 8KB trajectory AND build prefix-sum from registers ----
    {
        const float4* tr4 = reinterpret_cast<const float4*>(traj) + (size_t)b * (TT / 2);
        const float4 v = tr4[t];
        reinterpret_cast<float4*>(s)[t] = v;
        if (t < 4) s[TT + t] = make_float2(0.f, 0.f);

        const float q0 = v.x * v.x + v.y * v.y;
        const float q1 = v.z * v.z + v.w * v.w;
        const float tot = q0 + q1;
        float sc = tot;                                  // warp inclusive scan
#pragma unroll
        for (int o = 1; o < 32; o <<= 1) {
            const float n = __shfl_up_sync(0xffffffffu, sc, o);
            if (lane >= o) sc += n;
        }
        if (lane == 31) wtot[w] = sc;
        __syncthreads();
        float base = sc - tot;
#pragma unroll
        for (int k = 0; k < 16; ++k) if (k < w) base += wtot[k];
        sQ[2 * t]     = base;
        sQ[2 * t + 1] = base + q0;
        if (t == NT - 1) sQ[TT] = base + tot;
        __syncthreads();                // covers s and sQ
    }

    const int L = lengths[b];

    // ---- correlation loop ----
    const int lag0 = 16 * w + 4 * y + 1;      // odd; lags lag0..lag0+3
    int np0 = L - lag0;   if (np0 < 0) np0 = 0;
    int np3 = np0 - 3;    if (np3 < 0) np3 = 0;
    const int K = np3 >> 7;                   // unguarded 128-position rounds

    const unsigned sbase = (unsigned)__cvta_generic_to_shared(s);
    unsigned addr_a = sbase + 32u * (unsigned)lane;
    unsigned addr_e = sbase + (((unsigned)(lag0 - 1)) << 3) + 32u * (unsigned)lane;

    unsigned long long acc0 = 0, acc1 = 0, acc2 = 0, acc3 = 0;

    for (int it = 0; it < K; ++it) {
        unsigned long long a0, a1, a2, a3, e0, e1, e2, e3, e4, e5, e6, e7;
        asm("ld.shared.v2.b64 {%0,%1}, [%2];"    : "=l"(a0), "=l"(a1) : "r"(addr_a));
        asm("ld.shared.v2.b64 {%0,%1}, [%2+16];" : "=l"(a2), "=l"(a3) : "r"(addr_a));
        asm("ld.shared.v2.b64 {%0,%1}, [%2];"    : "=l"(e0), "=l"(e1) : "r"(addr_e));
        asm("ld.shared.v2.b64 {%0,%1}, [%2+16];" : "=l"(e2), "=l"(e3) : "r"(addr_e));
        asm("ld.shared.v2.b64 {%0,%1}, [%2+32];" : "=l"(e4), "=l"(e5) : "r"(addr_e));
        asm("ld.shared.v2.b64 {%0,%1}, [%2+48];" : "=l"(e6), "=l"(e7) : "r"(addr_e));
        // e index for (position i, lag lag0+j) is i+j+1
        FMA2(acc0, a0, e1); FMA2(acc0, a1, e2); FMA2(acc0, a2, e3); FMA2(acc0, a3, e4);
        FMA2(acc1, a0, e2); FMA2(acc1, a1, e3); FMA2(acc1, a2, e4); FMA2(acc1, a3, e5);
        FMA2(acc2, a0, e3); FMA2(acc2, a1, e4); FMA2(acc2, a2, e5); FMA2(acc2, a3, e6);
        FMA2(acc3, a0, e4); FMA2(acc3, a1, e5); FMA2(acc3, a2, e6); FMA2(acc3, a3, e7);
        addr_a += 1024;  addr_e += 1024;      // 128 positions * 8 B
    }

    float c0 = __uint_as_float((unsigned)acc0) + __uint_as_float((unsigned)(acc0 >> 32));
    float c1 = __uint_as_float((unsigned)acc1) + __uint_as_float((unsigned)(acc1 >> 32));
    float c2 = __uint_as_float((unsigned)acc2) + __uint_as_float((unsigned)(acc2 >> 32));
    float c3 = __uint_as_float((unsigned)acc3) + __uint_as_float((unsigned)(acc3 >> 32));

    // Guarded tail: positions [128K, np0), <= 5 rounds of 32.
    for (int p = (K << 7) + lane; p < np0; p += 32) {
        const float2 a = s[p];
        {
            const float2 e = s[p + lag0];
            c0 = fmaf(a.x, e.x, c0); c0 = fmaf(a.y, e.y, c0);
        }
        if (p < np0 - 1) {
            const float2 e = s[p + lag0 + 1];
            c1 = fmaf(a.x, e.x, c1); c1 = fmaf(a.y, e.y, c1);
        }
        if (p < np0 - 2) {
            const float2 e = s[p + lag0 + 2];
            c2 = fmaf(a.x, e.x, c2); c2 = fmaf(a.y, e.y, c2);
        }
        if (p < np0 - 3) {
            const float2 e = s[p + lag0 + 3];
            c3 = fmaf(a.x, e.x, c3); c3 = fmaf(a.y, e.y, c3);
        }
    }

#pragma unroll
    for (int o = 16; o; o >>= 1) {
        c0 += __shfl_xor_sync(0xffffffffu, c0, o);
        c1 += __shfl_xor_sync(0xffffffffu, c1, o);
        c2 += __shfl_xor_sync(0xffffffffu, c2, o);
        c3 += __shfl_xor_sync(0xffffffffu, c3, o);
    }
    // After the butterfly ALL lanes hold c0..c3. Lanes 0..3 each fit one lag.
    {
        const float alpha = alpha_pred[b];
        float rv1 = 0.f, rv2 = 0.f;
        if (lane < 4) {
            const float Ck  = (lane == 0) ? c0 : (lane == 1) ? c1 : (lane == 2) ? c2 : c3;
            const int   lag = lag0 + lane;
            const int   np  = L - lag;
            const int   cnt = (np > 0) ? np : 1;          // counts = max(#valid, 1)
            const float S   = (sQ[L] - sQ[lag]) + sQ[(np > 0) ? np : 0] - 2.f * Ck;
            const float lm  = logf(S / (float)cnt + 1e-8f);
            const float ll  = logf((float)lag);
            const float m   = (L > lag) ? 1.f : 0.f;
            const float r   = (lm - alpha * ll) * m;
            rv1 = r;
            rv2 = r * r;          // note: m^2 == m, so r^2 carries the mask
        }
        // sum over lanes 0..3 (quad-local butterfly; other quads hold zeros)
        rv1 += __shfl_xor_sync(0xffffffffu, rv1, 1);
        rv1 += __shfl_xor_sync(0xffffffffu, rv1, 2);
        rv2 += __shfl_xor_sync(0xffffffffu, rv2, 1);
        rv2 += __shfl_xor_sync(0xffffffffu, rv2, 2);
        if (lane == 0) { shr[w] = rv1; shr[16 + w] = rv2; }
    }
    __syncthreads();

    // ---- publish block partials; single global rendezvous ----
    if (t == 0) {
        float R1 = 0.f, R2 = 0.f;
#pragma unroll
        for (int k = 0; k < 16; ++k) { R1 += shr[k]; R2 += shr[16 + k]; }
        const int blk = 4 * b + y;
        g_R1[blk] = R1;
        g_R2[blk] = R2;
        __threadfence();
        const int old = atomicAdd(&g_done, 1);
        flag_all = (old == 4 * BB - 1) ? 1 : 0;
        if (old == 4 * BB - 1) __threadfence();   // acquire side
    }
    __syncthreads();
    if (!flag_all) return;

    // ---- globally-last block: combine per-batch, mean over batches ----
    if (t < 32) {
        float acc = 0.f;
#pragma unroll
        for (int h = 0; h < 2; ++h) {
            const int bb = t + 32 * h;
            float R1 = 0.f, R2 = 0.f;
#pragma unroll
            for (int yy = 0; yy < 4; ++yy) {
                R1 += __ldcg(&g_R1[4 * bb + yy]);
                R2 += __ldcg(&g_R2[4 * bb + yy]);
            }
            const int Lb = lengths[bb];
            int Mi = Lb - 1;  if (Mi < 0) Mi = 0;  if (Mi > MAXLAG) Mi = MAXLAG;
            const float M     = (float)Mi;
            const float denom = (M > 1.f) ? M : 1.f;
            const float inter = R1 / denom;
            // sum((intercept - resid)^2 * m) = R2 - 2*inter*R1 + inter^2*M
            acc += (R2 - 2.f * inter * R1 + inter * inter * M) / denom;
        }
#pragma unroll
        for (int o = 16; o; o >>= 1) acc += __shfl_xor_sync(0xffffffffu, acc, o);
        if (t == 0) {
            out[0] = acc / (float)BB;
            g_done = 0;                 // reset for next graph replay
        }
    }
}

extern "C" void kernel_launch(void* const* d_in, const int* in_sizes, int n_in,
                              void* d_out, int out_size)
{
    const float* alpha_pred = (const float*)d_in[0];
    const float* trajectory = (const float*)d_in[1];
    const int*   lengths    = (const int*)d_in[2];
    float* out = (float*)d_out;

    dim3 g1(BB, 4, 1);
    physics_kernel<<<g1, NT>>>(trajectory, alpha_pred, lengths, out);
}

// round 15
// speedup vs baseline: 1.2973x; 1.1597x over previous
#include <cuda_runtime.h>
#include <cuda_bf16.h>
#include <math.h>

#define BB 64
#define TT 1024
#define MAXLAG 256
#define NT 512

// Cross-block scratch (device globals — no allocation allowed).
__device__ float g_R1[BB * 4];       // per-block partial sum(resid*m)
__device__ float g_R2[BB * 4];       // per-block partial sum(resid^2*m)
__device__ int   g_done = 0;         // global finalize counter (self-resetting)

// Fused kernel, square form + linearized LOCAL fit:
//   per_traj = (R2 - 2*inter*R1 + inter^2*M)/denom,  inter = R1/denom
//   R1 = sum_l resid_l*m_l,  R2 = sum_l resid_l^2*m_l  (linear over lags!)
// grid = (64 batches, 4), 512 threads (16 warps) — best-measured shape.
// Warp w of block (b,y) owns lags lag_k = 4w+y+1+64k (k=0..3), stride-4
// interleave => blocks/warps balanced to <1%. After the warp butterfly every
// lane holds all four S[lag] values; lanes 0..3 fit one lag each (4 parallel
// logf), quad-reduce to (R1,R2), block-reduce, publish 2 scalars.
// ONE global rendezvous; the last block combines.
__global__ __launch_bounds__(NT) void physics_kernel(
    const float* __restrict__ traj,
    const float* __restrict__ alpha_pred,
    const int* __restrict__ lengths,
    float* __restrict__ out)
{
    __shared__ __align__(16) float2 s[TT];
    __shared__ float shr[32];             // r1[0..15], r2[16..31]
    __shared__ int flag_all;

    const int b = blockIdx.x;
    const int y = blockIdx.y;
    const int t    = threadIdx.x;
    const int w    = t >> 5;
    const int lane = t & 31;

    // 8KB trajectory load: 1 LDG.128 per thread.
    {
        const float4* tr4 = reinterpret_cast<const float4*>(traj) + (size_t)b * (TT / 2);
        reinterpret_cast<float4*>(s)[t] = tr4[t];
    }
    __syncthreads();

    const int L = lengths[b];

    // ---- MSD phase (round-11 loop, verbatim) ----
    const int lam = 4 * w + y + 1;                 // lag_k = lam + 64k
    int np0 = L - lam;          if (np0 < 0) np0 = 0;
    int np1 = np0 - 64;         if (np1 < 0) np1 = 0;
    int np2 = np0 - 128;        if (np2 < 0) np2 = 0;
    int np3 = np0 - 192;        if (np3 < 0) np3 = 0;
    const int K = np3 >> 5;                        // unguarded 32-position rounds

    const unsigned long long* s8 = reinterpret_cast<const unsigned long long*>(s);
    const unsigned long long NEG1 = 0xBF800000BF800000ULL;   // {-1.f,-1.f}
    unsigned long long acc0 = 0, acc1 = 0, acc2 = 0, acc3 = 0;

    {
        int p = lane;
        for (int it = 0; it < K; ++it, p += 32) {
            const unsigned long long a  = s8[p];
            const unsigned long long e0 = s8[p + lam];
            const unsigned long long e1 = s8[p + lam + 64];
            const unsigned long long e2 = s8[p + lam + 128];
            const unsigned long long e3 = s8[p + lam + 192];
            unsigned long long d;
            asm("fma.rn.f32x2 %0, %1, %2, %3;" : "=l"(d) : "l"(a), "l"(NEG1), "l"(e0));
            asm("fma.rn.f32x2 %0, %1, %1, %0;" : "+l"(acc0) : "l"(d));
            asm("fma.rn.f32x2 %0, %1, %2, %3;" : "=l"(d) : "l"(a), "l"(NEG1), "l"(e1));
            asm("fma.rn.f32x2 %0, %1, %1, %0;" : "+l"(acc1) : "l"(d));
            asm("fma.rn.f32x2 %0, %1, %2, %3;" : "=l"(d) : "l"(a), "l"(NEG1), "l"(e2));
            asm("fma.rn.f32x2 %0, %1, %1, %0;" : "+l"(acc2) : "l"(d));
            asm("fma.rn.f32x2 %0, %1, %2, %3;" : "=l"(d) : "l"(a), "l"(NEG1), "l"(e3));
            asm("fma.rn.f32x2 %0, %1, %1, %0;" : "+l"(acc3) : "l"(d));
        }
    }

    float f0 = __uint_as_float((unsigned)acc0) + __uint_as_float((unsigned)(acc0 >> 32));
    float f1 = __uint_as_float((unsigned)acc1) + __uint_as_float((unsigned)(acc1 >> 32));
    float f2 = __uint_as_float((unsigned)acc2) + __uint_as_float((unsigned)(acc2 >> 32));
    float f3 = __uint_as_float((unsigned)acc3) + __uint_as_float((unsigned)(acc3 >> 32));

    // Guarded tail: positions [32K, np0), ~6 rounds of 32 max.
    for (int p = (K << 5) + lane; p < np0; p += 32) {
        const float2 a = s[p];
        {
            const float2 e = s[p + lam];
            const float dx = e.x - a.x, dy = e.y - a.y;
            f0 = fmaf(dx, dx, f0); f0 = fmaf(dy, dy, f0);
        }
        if (p < np1) {
            const float2 e = s[p + lam + 64];
            const float dx = e.x - a.x, dy = e.y - a.y;
            f1 = fmaf(dx, dx, f1); f1 = fmaf(dy, dy, f1);
        }
        if (p < np2) {
            const float2 e = s[p + lam + 128];
            const float dx = e.x - a.x, dy = e.y - a.y;
            f2 = fmaf(dx, dx, f2); f2 = fmaf(dy, dy, f2);
        }
        if (p < np3) {
            const float2 e = s[p + lam + 192];
            const float dx = e.x - a.x, dy = e.y - a.y;
            f3 = fmaf(dx, dx, f3); f3 = fmaf(dy, dy, f3);
        }
    }

#pragma unroll
    for (int o = 16; o; o >>= 1) {
        f0 += __shfl_xor_sync(0xffffffffu, f0, o);
        f1 += __shfl_xor_sync(0xffffffffu, f1, o);
        f2 += __shfl_xor_sync(0xffffffffu, f2, o);
        f3 += __shfl_xor_sync(0xffffffffu, f3, o);
    }

    // ---- local fit: lanes 0..3 each fit one of this warp's 4 lags ----
    {
        const float alpha = alpha_pred[b];
        float rv1 = 0.f, rv2 = 0.f;
        if (lane < 4) {
            const float S   = (lane == 0) ? f0 : (lane == 1) ? f1 : (lane == 2) ? f2 : f3;
            const int   lag = lam + 64 * lane;
            const int   np  = L - lag;
            const int   cnt = (np > 0) ? np : 1;          // counts = max(#valid, 1)
            const float lm  = logf(S / (float)cnt + 1e-8f);
            const float ll  = logf((float)lag);
            const float m   = (L > lag) ? 1.f : 0.f;
            const float r   = (lm - alpha * ll) * m;      // masked residual
            rv1 = r;
            rv2 = r * r;                                  // m^2 == m
        }
        // quad-local butterfly (other quads hold zeros)
        rv1 += __shfl_xor_sync(0xffffffffu, rv1, 1);
        rv1 += __shfl_xor_sync(0xffffffffu, rv1, 2);
        rv2 += __shfl_xor_sync(0xffffffffu, rv2, 1);
        rv2 += __shfl_xor_sync(0xffffffffu, rv2, 2);
        if (lane == 0) { shr[w] = rv1; shr[16 + w] = rv2; }
    }
    __syncthreads();

    // ---- publish block partials; single global rendezvous ----
    if (t == 0) {
        float R1 = 0.f, R2 = 0.f;
#pragma unroll
        for (int k = 0; k < 16; ++k) { R1 += shr[k]; R2 += shr[16 + k]; }
        const int blk = 4 * b + y;
        g_R1[blk] = R1;
        g_R2[blk] = R2;
        __threadfence();
        const int old = atomicAdd(&g_done, 1);
        flag_all = (old == 4 * BB - 1) ? 1 : 0;
        if (old == 4 * BB - 1) __threadfence();   // acquire side
    }
    __syncthreads();
    if (!flag_all) return;

    // ---- globally-last block: combine per-batch, mean over batches ----
    if (t < 32) {
        float acc = 0.f;
#pragma unroll
        for (int h = 0; h < 2; ++h) {
            const int bb = t + 32 * h;
            float R1 = 0.f, R2 = 0.f;
#pragma unroll
            for (int yy = 0; yy < 4; ++yy) {
                R1 += __ldcg(&g_R1[4 * bb + yy]);
                R2 += __ldcg(&g_R2[4 * bb + yy]);
            }
            const int Lb = lengths[bb];
            int Mi = Lb - 1;  if (Mi < 0) Mi = 0;  if (Mi > MAXLAG) Mi = MAXLAG;
            const float M     = (float)Mi;
            const float denom = (M > 1.f) ? M : 1.f;
            const float inter = R1 / denom;
            // sum((intercept - resid)^2 * m) = R2 - 2*inter*R1 + inter^2*M
            acc += (R2 - 2.f * inter * R1 + inter * inter * M) / denom;
        }
#pragma unroll
        for (int o = 16; o; o >>= 1) acc += __shfl_xor_sync(0xffffffffu, acc, o);
        if (t == 0) {
            out[0] = acc / (float)BB;
            g_done = 0;                 // reset for next graph replay
        }
    }
}

extern "C" void kernel_launch(void* const* d_in, const int* in_sizes, int n_in,
                              void* d_out, int out_size)
{
    const float* alpha_pred = (const float*)d_in[0];
    const float* trajectory = (const float*)d_in[1];
    const int*   lengths    = (const int*)d_in[2];
    float* out = (float*)d_out;

    dim3 g1(BB, 4, 1);
    physics_kernel<<<g1, NT>>>(trajectory, alpha_pred, lengths, out);
}